// round 1
// baseline (speedup 1.0000x reference)
#include <cuda_runtime.h>
#include <cuda_bf16.h>

// ---------------------------------------------------------------------------
// SchNet on GB300: per-molecule dense formulation.
// M=2048 molecules, A=24 atoms, fully connected (BOX=4 < CUTOFF=10) so the
// edge set is all ordered pairs (s,d), s!=d. We store edge state as
// EA[m][d][s][128] (diag rows computed but masked out of aggregation).
// ---------------------------------------------------------------------------

#define Mmol   2048
#define Aat    24
#define Nnode  (Mmol*Aat)           // 49152
#define EPM    (Aat*Aat)            // 576 rows per molecule (incl diag)
#define HF     128

typedef unsigned long long u64;

// Scratch (device globals -- no allocation allowed)
__device__ float g_EA [(size_t)Mmol*EPM*HF];   // ~604 MB
__device__ float g_h  [(size_t)Nnode*HF];
__device__ float g_x  [(size_t)Nnode*HF];
__device__ float g_agg[(size_t)Nnode*HF];

// ---------------------------------------------------------------------------
// helpers
// ---------------------------------------------------------------------------
__device__ __forceinline__ u64 pk2(float v){ u64 r; asm("mov.b64 %0, {%1, %1};" : "=l"(r) : "f"(v)); return r; }
__device__ __forceinline__ float2 upk(u64 v){ float2 f; asm("mov.b64 {%0, %1}, %2;" : "=f"(f.x), "=f"(f.y) : "l"(v)); return f; }
#define FFMA2(a,b,c) asm("fma.rn.f32x2 %0, %1, %2, %0;" : "+l"(a) : "l"(b), "l"(c))

__device__ __forceinline__ float ssp(float x){
    // softplus(x) - log(2), numerically stable
    return fmaxf(x, 0.f) + __logf(1.f + __expf(-fabsf(x))) - 0.6931471805599453f;
}

// 32-row x 128-col GEMM tile: acc += inD^T * W.
// inD: [128][33] duplicated pairs (u64 = {v,v}), W: [128][128] row-major smem.
// Thread (tc in 0..15, tr in 0..15): cols cbase=tc*8..+7 (4 pairs), rows r0=tr*2, r0+1.
__device__ __forceinline__ void gemm32x128(const float* __restrict__ Ws,
                                           const u64* __restrict__ inD,
                                           int cbase, int r0, u64 acc[8]) {
    #pragma unroll 8
    for (int k = 0; k < 128; ++k) {
        u64 a0 = inD[k*33 + r0];
        u64 a1 = inD[k*33 + r0 + 1];
        const float* wr = Ws + k*128 + cbase;
        ulonglong2 wA = *(const ulonglong2*)(wr);
        ulonglong2 wB = *(const ulonglong2*)(wr + 4);
        FFMA2(acc[0], a0, wA.x); FFMA2(acc[1], a0, wA.y);
        FFMA2(acc[2], a0, wB.x); FFMA2(acc[3], a0, wB.y);
        FFMA2(acc[4], a1, wA.x); FFMA2(acc[5], a1, wA.y);
        FFMA2(acc[6], a1, wB.x); FFMA2(acc[7], a1, wB.y);
    }
}

// stage 32 rows x 128 floats from global (row-major) into duplicated transposed
// smem inD[k][r] = {v,v}
__device__ __forceinline__ void stage32(u64* __restrict__ inD, const float4* __restrict__ src, int tid){
    #pragma unroll
    for (int i = 0; i < 4; ++i) {
        int idx = tid + i*256;        // = r*32 + k4
        int r  = idx >> 5;
        int k4 = idx & 31;
        float4 v = src[idx];
        u64* d = inD + (k4*4)*33 + r;
        d[0]  = pk2(v.x);
        d[33] = pk2(v.y);
        d[66] = pk2(v.z);
        d[99] = pk2(v.w);
    }
}

// ---------------------------------------------------------------------------
// init kernels
// ---------------------------------------------------------------------------
__global__ void k_init_h(const int* __restrict__ charges, const float* __restrict__ emb){
    int idx = blockIdx.x*256 + threadIdx.x;      // < Nnode*128
    int node = idx >> 7, f = idx & 127;
    g_h[idx] = emb[charges[node]*128 + f];
}

__global__ void k_init_ea(const float* __restrict__ coords){
    int w    = (blockIdx.x*256 + threadIdx.x) >> 5;   // warp id = edge row
    int lane = threadIdx.x & 31;
    int m = w / EPM, rr = w % EPM;
    int d = rr / Aat, s = rr % Aat;
    int ns = m*Aat + s, nd = m*Aat + d;
    float dx = coords[ns*3+0] - coords[nd*3+0];
    float dy = coords[ns*3+1] - coords[nd*3+1];
    float dz = coords[ns*3+2] - coords[nd*3+2];
    float dist = sqrtf(dx*dx + dy*dy + dz*dz);
    const float delta = 10.0f/127.0f;
    const float coeff = -0.5f/(delta*delta);
    float* row = g_EA + (size_t)w*128;
    #pragma unroll
    for (int i = 0; i < 4; ++i) {
        int gg = lane + 32*i;
        float od = dist - delta*(float)gg;
        row[gg] = __expf(coeff*od*od);
    }
}

// ---------------------------------------------------------------------------
// x = h @ node_lin_w  (single GEMM, no bias/act)
// grid 384 blocks x 4 tiles of 32 rows
// ---------------------------------------------------------------------------
__global__ void __launch_bounds__(256) k_x(const float* __restrict__ nlw){
    extern __shared__ float sm[];
    float* w1s = sm;                       // 16384 floats
    u64*   inD = (u64*)(sm + 16384);       // 4224 u64

    const int tid = threadIdx.x;
    const int tc = tid & 15, tr = tid >> 4;
    const int cbase = tc*8, r0 = tr*2;

    {
        const float4* a = (const float4*)nlw;
        float4* pa = (float4*)w1s;
        for (int i = tid; i < 4096; i += 256) pa[i] = a[i];
    }
    __syncthreads();

    for (int t = 0; t < 4; ++t) {
        int rowbase = (blockIdx.x*4 + t)*32;
        stage32(inD, (const float4*)(g_h + (size_t)rowbase*128), tid);
        __syncthreads();
        u64 acc[8] = {0,0,0,0,0,0,0,0};
        gemm32x128(w1s, inD, cbase, r0, acc);
        #pragma unroll
        for (int ri = 0; ri < 2; ++ri) {
            int row = rowbase + r0 + ri;
            float2 f0 = upk(acc[ri*4+0]), f1 = upk(acc[ri*4+1]);
            float2 f2 = upk(acc[ri*4+2]), f3 = upk(acc[ri*4+3]);
            float4 o0 = make_float4(f0.x, f0.y, f1.x, f1.y);
            float4 o1 = make_float4(f2.x, f2.y, f3.x, f3.y);
            *(float4*)(g_x + (size_t)row*128 + cbase)     = o0;
            *(float4*)(g_x + (size_t)row*128 + cbase + 4) = o1;
        }
        __syncthreads();   // inD reused next tile
    }
}

// ---------------------------------------------------------------------------
// edge kernel: per molecule.
//   W = ssp(EA@e_w1+b1)@e_w2+b2 ; EA_new = x[s]*W ; agg[d] = sum_s EA_new
// ---------------------------------------------------------------------------
__global__ void __launch_bounds__(256) k_edge(const float* __restrict__ ew1, const float* __restrict__ eb1,
                                              const float* __restrict__ ew2, const float* __restrict__ eb2)
{
    extern __shared__ float sm[];
    float* w1s = sm;                        // 16384
    float* w2s = sm + 16384;                // 16384
    u64*  inD  = (u64*)(sm + 32768);        // 4224
    u64*  midD = inD + 4224;                // 4224
    float* xs  = (float*)(midD + 4224);     // 3072

    const int tid = threadIdx.x;
    const int m = blockIdx.x;
    const int tc = tid & 15, tr = tid >> 4;
    const int cbase = tc*8, r0 = tr*2;

    {
        const float4* a = (const float4*)ew1;
        const float4* b = (const float4*)ew2;
        float4* pa = (float4*)w1s; float4* pb = (float4*)w2s;
        for (int i = tid; i < 4096; i += 256) { pa[i] = a[i]; pb[i] = b[i]; }
        const float4* xg = (const float4*)(g_x + (size_t)m*Aat*128);
        float4* px = (float4*)xs;
        for (int i = tid; i < 768; i += 256) px[i] = xg[i];
    }
    float b1r[8], b2r[8];
    #pragma unroll
    for (int u = 0; u < 8; ++u) { b1r[u] = eb1[cbase+u]; b2r[u] = eb2[cbase+u]; }
    __syncthreads();

    float* eaBase = g_EA + (size_t)m*EPM*128;

    for (int tile = 0; tile < 18; ++tile) {
        stage32(inD, (const float4*)(eaBase + (size_t)tile*32*128), tid);
        __syncthreads();

        u64 acc[8] = {0,0,0,0,0,0,0,0};
        gemm32x128(w1s, inD, cbase, r0, acc);

        // ssp + bias -> duplicated mid
        #pragma unroll
        for (int i = 0; i < 8; ++i) {
            float2 f = upk(acc[i]);
            int ri = i >> 2, cp = i & 3;
            f.x = ssp(f.x + b1r[cp*2]);
            f.y = ssp(f.y + b1r[cp*2+1]);
            midD[(cbase + cp*2    )*33 + r0 + ri] = pk2(f.x);
            midD[(cbase + cp*2 + 1)*33 + r0 + ri] = pk2(f.y);
        }
        __syncthreads();

        #pragma unroll
        for (int i = 0; i < 8; ++i) acc[i] = 0;
        gemm32x128(w2s, midD, cbase, r0, acc);

        // epilogue: +b2, * x[s], store EA row
        #pragma unroll
        for (int ri = 0; ri < 2; ++ri) {
            int rr = tile*32 + r0 + ri;       // rr = d*24 + s
            int s = rr % Aat;
            float4 xv0 = *(const float4*)(xs + s*128 + cbase);
            float4 xv1 = *(const float4*)(xs + s*128 + cbase + 4);
            float2 f0 = upk(acc[ri*4+0]), f1 = upk(acc[ri*4+1]);
            float2 f2 = upk(acc[ri*4+2]), f3 = upk(acc[ri*4+3]);
            float4 o0, o1;
            o0.x = (f0.x + b2r[0]) * xv0.x;  o0.y = (f0.y + b2r[1]) * xv0.y;
            o0.z = (f1.x + b2r[2]) * xv0.z;  o0.w = (f1.y + b2r[3]) * xv0.w;
            o1.x = (f2.x + b2r[4]) * xv1.x;  o1.y = (f2.y + b2r[5]) * xv1.y;
            o1.z = (f3.x + b2r[6]) * xv1.z;  o1.w = (f3.y + b2r[7]) * xv1.w;
            *(float4*)(eaBase + (size_t)rr*128 + cbase)     = o0;
            *(float4*)(eaBase + (size_t)rr*128 + cbase + 4) = o1;
        }
        // no trailing sync needed: buffer hazards covered by the two syncs above
    }
    __syncthreads();   // make all EA writes visible block-wide

    // agg[d][j] = sum_{s != d} EA[d][s][j]   (L2-hot: we just wrote it)
    float* aggBase = g_agg + (size_t)m*Aat*128;
    for (int o = tid; o < Aat*128; o += 256) {
        int d = o >> 7, j = o & 127;
        const float* col = eaBase + (size_t)d*Aat*128 + j;
        float ssum = 0.f;
        #pragma unroll
        for (int s = 0; s < Aat; ++s) ssum += col[s*128];
        ssum -= col[d*128];               // mask diagonal
        aggBase[o] = ssum;
    }
}

// ---------------------------------------------------------------------------
// node kernel: h += ssp(agg@n_w1+b1)@n_w2+b2
// grid 384 blocks x 4 tiles of 32 rows
// ---------------------------------------------------------------------------
__global__ void __launch_bounds__(256) k_node(const float* __restrict__ nw1, const float* __restrict__ nb1,
                                              const float* __restrict__ nw2, const float* __restrict__ nb2)
{
    extern __shared__ float sm[];
    float* w1s = sm;
    float* w2s = sm + 16384;
    u64*  inD  = (u64*)(sm + 32768);
    u64*  midD = inD + 4224;

    const int tid = threadIdx.x;
    const int tc = tid & 15, tr = tid >> 4;
    const int cbase = tc*8, r0 = tr*2;

    {
        const float4* a = (const float4*)nw1;
        const float4* b = (const float4*)nw2;
        float4* pa = (float4*)w1s; float4* pb = (float4*)w2s;
        for (int i = tid; i < 4096; i += 256) { pa[i] = a[i]; pb[i] = b[i]; }
    }
    float b1r[8], b2r[8];
    #pragma unroll
    for (int u = 0; u < 8; ++u) { b1r[u] = nb1[cbase+u]; b2r[u] = nb2[cbase+u]; }
    __syncthreads();

    for (int t = 0; t < 4; ++t) {
        int rowbase = (blockIdx.x*4 + t)*32;
        stage32(inD, (const float4*)(g_agg + (size_t)rowbase*128), tid);
        __syncthreads();

        u64 acc[8] = {0,0,0,0,0,0,0,0};
        gemm32x128(w1s, inD, cbase, r0, acc);
        #pragma unroll
        for (int i = 0; i < 8; ++i) {
            float2 f = upk(acc[i]);
            int ri = i >> 2, cp = i & 3;
            f.x = ssp(f.x + b1r[cp*2]);
            f.y = ssp(f.y + b1r[cp*2+1]);
            midD[(cbase + cp*2    )*33 + r0 + ri] = pk2(f.x);
            midD[(cbase + cp*2 + 1)*33 + r0 + ri] = pk2(f.y);
        }
        __syncthreads();

        #pragma unroll
        for (int i = 0; i < 8; ++i) acc[i] = 0;
        gemm32x128(w2s, midD, cbase, r0, acc);

        #pragma unroll
        for (int ri = 0; ri < 2; ++ri) {
            int row = rowbase + r0 + ri;
            float* hp = g_h + (size_t)row*128 + cbase;
            float4 h0 = *(float4*)(hp);
            float4 h1 = *(float4*)(hp + 4);
            float2 f0 = upk(acc[ri*4+0]), f1 = upk(acc[ri*4+1]);
            float2 f2 = upk(acc[ri*4+2]), f3 = upk(acc[ri*4+3]);
            h0.x += f0.x + b2r[0];  h0.y += f0.y + b2r[1];
            h0.z += f1.x + b2r[2];  h0.w += f1.y + b2r[3];
            h1.x += f2.x + b2r[4];  h1.y += f2.y + b2r[5];
            h1.z += f3.x + b2r[6];  h1.w += f3.y + b2r[7];
            *(float4*)(hp)     = h0;
            *(float4*)(hp + 4) = h1;
        }
    }
}

// ---------------------------------------------------------------------------
// graph readout: out[m] = sum_s ( ssp(h[s]@g_w1+b1)@g_w2 + b2 )
// ---------------------------------------------------------------------------
__global__ void __launch_bounds__(256) k_graph(const float* __restrict__ gw1, const float* __restrict__ gb1,
                                               const float* __restrict__ gw2, const float* __restrict__ gb2,
                                               float* __restrict__ out)
{
    __shared__ float hs[Aat*128];     // 12 KB
    __shared__ float w1s[128*64];     // 32 KB
    __shared__ float red[256];
    const int tid = threadIdx.x;
    const int m = blockIdx.x;

    {
        const float4* hg = (const float4*)(g_h + (size_t)m*Aat*128);
        float4* ph = (float4*)hs;
        for (int i = tid; i < 768; i += 256) ph[i] = hg[i];
        const float4* wg = (const float4*)gw1;
        float4* pw = (float4*)w1s;
        for (int i = tid; i < 2048; i += 256) pw[i] = wg[i];
    }
    __syncthreads();

    float local = 0.f;
    for (int pos = tid; pos < Aat*64; pos += 256) {
        int s = pos >> 6, c = pos & 63;
        float acc = gb1[c];
        #pragma unroll 16
        for (int k = 0; k < 128; ++k) acc += hs[s*128+k] * w1s[k*64+c];
        local += ssp(acc) * gw2[c];
    }
    red[tid] = local;
    __syncthreads();
    #pragma unroll
    for (int off = 128; off > 0; off >>= 1) {
        if (tid < off) red[tid] += red[tid+off];
        __syncthreads();
    }
    if (tid == 0) out[m] = red[0] + (float)Aat * gb2[0];
}

// ---------------------------------------------------------------------------
// launch
// ---------------------------------------------------------------------------
extern "C" void kernel_launch(void* const* d_in, const int* in_sizes, int n_in,
                              void* d_out, int out_size)
{
    const int*   charges = (const int*)  d_in[0];
    const float* coords  = (const float*)d_in[1];
    // d_in[2] node_batch_vec, d_in[3] edge_index: structure is deterministic, unused
    const float* emb = (const float*)d_in[4];
    const float* nlw = (const float*)d_in[5];
    const float* ew1 = (const float*)d_in[6];
    const float* eb1 = (const float*)d_in[7];
    const float* ew2 = (const float*)d_in[8];
    const float* eb2 = (const float*)d_in[9];
    const float* nw1 = (const float*)d_in[10];
    const float* nb1 = (const float*)d_in[11];
    const float* nw2 = (const float*)d_in[12];
    const float* nb2 = (const float*)d_in[13];
    const float* gw1 = (const float*)d_in[14];
    const float* gb1 = (const float*)d_in[15];
    const float* gw2 = (const float*)d_in[16];
    const float* gb2 = (const float*)d_in[17];
    float* out = (float*)d_out;

    const int SM_EDGE = 16384*2*4 + 4224*8*2 + 3072*4;   // 210944 B
    const int SM_NODE = 16384*2*4 + 4224*8*2;            // 198656 B
    const int SM_X    = 16384*4 + 4224*8;                // 99328 B
    cudaFuncSetAttribute(k_edge, cudaFuncAttributeMaxDynamicSharedMemorySize, SM_EDGE);
    cudaFuncSetAttribute(k_node, cudaFuncAttributeMaxDynamicSharedMemorySize, SM_NODE);
    cudaFuncSetAttribute(k_x,    cudaFuncAttributeMaxDynamicSharedMemorySize, SM_X);

    k_init_h <<<(Nnode*128)/256, 256>>>(charges, emb);
    k_init_ea<<<(Mmol*EPM*32)/256, 256>>>(coords);

    for (int l = 0; l < 4; ++l) {
        k_x   <<<384, 256, SM_X>>>(nlw);
        k_edge<<<Mmol, 256, SM_EDGE>>>(ew1, eb1, ew2, eb2);
        k_node<<<384, 256, SM_NODE>>>(nw1, nb1, nw2, nb2);
    }
    k_graph<<<Mmol, 256>>>(gw1, gb1, gw2, gb2, out);
}